// round 4
// baseline (speedup 1.0000x reference)
#include <cuda_runtime.h>
#include <cuda_fp16.h>
#include <stdint.h>
#include <math.h>

// ---------------- problem constants ------------------------------------------
#define H_DIM  2048
#define E_NUM  16
#define F_DIM  1408
#define FS_DIM 4096
#define T_NUM  2048   // B*S
#define TOPK   4
#define CAP    2048

// ---------------- GEMM tiling ------------------------------------------------
#define BM 128
#define BN 128
#define BK 64
#define STAGES 3
#define KSTR 72        // A smem row stride (halves): 144B -> conflict-free
#define BSTR 136       // B smem row stride (halves): 272B -> conflict-free trans ldsm
#define A_H (BM * KSTR)          // 9216 halves
#define B_H (BK * BSTR)          // 8704 halves
#define GU_STAGE_H (A_H + 2 * B_H)
#define DN_STAGE_H (A_H + B_H)
#define GU_SMEM (GU_STAGE_H * STAGES * 2)   // 159744 B
#define DN_SMEM (DN_STAGE_H * STAGES * 2)   // 107520 B

// ---------------- static scratch ---------------------------------------------
__device__ __half d_Xg[(size_t)E_NUM * CAP * H_DIM];     // gathered w*x (fp16)
__device__ __half d_xh[(size_t)T_NUM * H_DIM];           // fp16 x (shared expert)
__device__ __half d_hr[(size_t)E_NUM * CAP * F_DIM];     // routed h
__device__ __half d_hs[(size_t)T_NUM * FS_DIM];          // shared h
__device__ float  d_Yr[(size_t)E_NUM * CAP * H_DIM];     // routed down out per slot
__device__ __half d_WgH[(size_t)E_NUM * H_DIM * F_DIM];  // fp16, natural [e][H][F]
__device__ __half d_WuH[(size_t)E_NUM * H_DIM * F_DIM];
__device__ __half d_WdH[(size_t)E_NUM * F_DIM * H_DIM];  // [e][F][H]
__device__ __half d_WgsH[(size_t)H_DIM * FS_DIM];        // [H][FS]
__device__ __half d_WusH[(size_t)H_DIM * FS_DIM];
__device__ __half d_WdsH[(size_t)FS_DIM * H_DIM];        // [FS][H]
__device__ int    d_cnt[E_NUM];
__device__ int    d_t2s[T_NUM * TOPK];
__device__ float  d_t2w[T_NUM * TOPK];

// ---------------- helpers ----------------------------------------------------
__device__ __forceinline__ uint32_t sptr(const void* p) {
    return (uint32_t)__cvta_generic_to_shared(p);
}
__device__ __forceinline__ void cp16(uint32_t dst, const void* src) {
    asm volatile("cp.async.cg.shared.global [%0], [%1], 16;\n" :: "r"(dst), "l"(src));
}
__device__ __forceinline__ void cp16z(uint32_t dst, const void* src, bool pred) {
    int sz = pred ? 16 : 0;
    asm volatile("cp.async.cg.shared.global [%0], [%1], 16, %2;\n" :: "r"(dst), "l"(src), "r"(sz));
}
#define CP_COMMIT asm volatile("cp.async.commit_group;\n" ::: "memory")
#define CP_WAIT1  asm volatile("cp.async.wait_group 1;\n" ::: "memory")

__device__ __forceinline__ void ldm_x4(uint32_t* r, uint32_t addr) {
    asm volatile("ldmatrix.sync.aligned.m8n8.x4.shared.b16 {%0,%1,%2,%3}, [%4];\n"
                 : "=r"(r[0]), "=r"(r[1]), "=r"(r[2]), "=r"(r[3]) : "r"(addr));
}
__device__ __forceinline__ void ldm_x4t(uint32_t* r, uint32_t addr) {
    asm volatile("ldmatrix.sync.aligned.m8n8.x4.trans.shared.b16 {%0,%1,%2,%3}, [%4];\n"
                 : "=r"(r[0]), "=r"(r[1]), "=r"(r[2]), "=r"(r[3]) : "r"(addr));
}
__device__ __forceinline__ void mma16816(float* c, const uint32_t* a, const uint32_t* b) {
    asm volatile(
        "mma.sync.aligned.m16n8k16.row.col.f32.f16.f16.f32 "
        "{%0,%1,%2,%3}, {%4,%5,%6,%7}, {%8,%9}, {%0,%1,%2,%3};\n"
        : "+f"(c[0]), "+f"(c[1]), "+f"(c[2]), "+f"(c[3])
        : "r"(a[0]), "r"(a[1]), "r"(a[2]), "r"(a[3]), "r"(b[0]), "r"(b[1]));
}
__device__ __forceinline__ float silu_f(float g) {
    return g / (1.0f + __expf(-g));
}

// ---------------- kernel: streaming fp32 -> fp16 convert (3 tensors via z) ---
__global__ void convert3_f2h_kernel(const float* __restrict__ i0,
                                    const float* __restrict__ i1,
                                    const float* __restrict__ i2,
                                    __half* __restrict__ o0,
                                    __half* __restrict__ o1,
                                    __half* __restrict__ o2,
                                    size_t n4) {
    const float4* in4;
    uint2* out8;
    if (blockIdx.z == 0)      { in4 = (const float4*)i0; out8 = (uint2*)o0; }
    else if (blockIdx.z == 1) { in4 = (const float4*)i1; out8 = (uint2*)o1; }
    else                      { in4 = (const float4*)i2; out8 = (uint2*)o2; }
    size_t idx = (size_t)blockIdx.x * blockDim.x + threadIdx.x;
    size_t stride = (size_t)gridDim.x * blockDim.x;
    for (size_t i = idx; i < n4; i += stride) {
        float4 v = in4[i];
        union { __half2 h[2]; uint2 u; } r;
        r.h[0] = __floats2half2_rn(v.x, v.y);
        r.h[1] = __floats2half2_rn(v.z, v.w);
        out8[i] = r.u;
    }
}

// ---------------- kernel: zero counters --------------------------------------
__global__ void moe_zero_cnt_kernel(int* cnt) {
    if (threadIdx.x < E_NUM) cnt[threadIdx.x] = 0;
}

// ---------------- kernel: router + softmax + top4 + gather -------------------
__global__ void moe_router_kernel(const float* __restrict__ x,
                                  const float* __restrict__ wr,
                                  __half* __restrict__ xh,
                                  __half* __restrict__ Xg,
                                  int* __restrict__ cnt,
                                  int* __restrict__ t2s,
                                  float* __restrict__ t2w) {
    __shared__ float xs[H_DIM];
    __shared__ float logits[E_NUM];
    __shared__ int   sel_slot[TOPK];
    __shared__ float sel_w[TOPK];

    const int t = blockIdx.x;
    const int tid = threadIdx.x;
    const int lane = tid & 31;
    const int warp = tid >> 5;

    for (int i = tid; i < H_DIM; i += 128) xs[i] = x[(size_t)t * H_DIM + i];
    __syncthreads();

    for (int e = warp * 4; e < warp * 4 + 4; e++) {
        float s = 0.f;
        const float* wre = wr + (size_t)e * H_DIM;
        for (int h = lane; h < H_DIM; h += 32) s += xs[h] * wre[h];
        #pragma unroll
        for (int off = 16; off; off >>= 1) s += __shfl_xor_sync(0xffffffffu, s, off);
        if (lane == 0) logits[e] = s;
    }
    __syncthreads();

    if (tid == 0) {
        float p[E_NUM];
        float mx = -1e30f;
        #pragma unroll
        for (int e = 0; e < E_NUM; e++) mx = fmaxf(mx, logits[e]);
        #pragma unroll
        for (int e = 0; e < E_NUM; e++) p[e] = expf(logits[e] - mx);
        float tw = 0.f;
        for (int j = 0; j < TOPK; j++) {
            int am = 0; float bv = -1.f;
            #pragma unroll
            for (int e = 0; e < E_NUM; e++) { if (p[e] > bv) { bv = p[e]; am = e; } }
            int pos = atomicAdd(&cnt[am], 1);
            sel_slot[j] = am * CAP + pos;
            sel_w[j]    = bv;
            tw += bv;
            p[am] = -2.f;
        }
        float inv = 1.f / tw;
        for (int j = 0; j < TOPK; j++) {
            float w = sel_w[j] * inv;
            sel_w[j] = w;
            t2s[t * TOPK + j] = sel_slot[j];
            t2w[t * TOPK + j] = w;
        }
    }
    __syncthreads();

    const int s0 = sel_slot[0], s1 = sel_slot[1], s2 = sel_slot[2], s3 = sel_slot[3];
    const float w0 = sel_w[0], w1 = sel_w[1], w2 = sel_w[2], w3 = sel_w[3];
    for (int i = tid; i < H_DIM; i += 128) {
        float v = xs[i];
        xh[(size_t)t * H_DIM + i]  = __float2half(v);
        Xg[(size_t)s0 * H_DIM + i] = __float2half(w0 * v);
        Xg[(size_t)s1 * H_DIM + i] = __float2half(w1 * v);
        Xg[(size_t)s2 * H_DIM + i] = __float2half(w2 * v);
        Xg[(size_t)s3 * H_DIM + i] = __float2half(w3 * v);
    }
}

// ---------------- kernel: fused gate/up GEMM + silu --------------------------
// C tile 128x128, 512 threads (16 warps 4x4, warp 32x32), cp.async 3-stage.
// A[m][k] fp16 row-major; Bg/Bu fp16 natural [k][n] (ldmatrix.trans).
template <bool ROUTED>
__global__ __launch_bounds__(512, 1)
void moe_gu_kernel(const __half* __restrict__ Abase,
                   const __half* __restrict__ BgAll,
                   const __half* __restrict__ BuAll,
                   __half* __restrict__ Hbase,
                   const int* __restrict__ cnt,
                   int F) {
    const int e = blockIdx.z;
    int M;
    const __half *A, *Bg, *Bu;
    __half* Hout;
    if (ROUTED) {
        M = cnt[e];
        A    = Abase + (size_t)e * CAP * H_DIM;
        Bg   = BgAll + (size_t)e * H_DIM * F;
        Bu   = BuAll + (size_t)e * H_DIM * F;
        Hout = Hbase + (size_t)e * CAP * F;
    } else {
        M = T_NUM; A = Abase; Bg = BgAll; Bu = BuAll; Hout = Hbase;
    }
    const int m0 = blockIdx.x * BM;
    if (m0 >= M) return;
    const int n0 = blockIdx.y * BN;

    extern __shared__ __half smem[];
    const int tid = threadIdx.x;
    const int lane = tid & 31;
    const int warp = tid >> 5;
    const int wm = warp >> 2, wn = warp & 3;

    auto load_stage = [&](int s, int k0) {
        __half* As  = smem + s * GU_STAGE_H;
        __half* Bgs = As + A_H;
        __half* Bus = Bgs + B_H;
        int c = tid;
        #pragma unroll
        for (int i = 0; i < 2; i++, c += 512) {         // A: 128 rows x 8 chunks
            int row = c >> 3, ch = c & 7;
            cp16z(sptr(As + row * KSTR + ch * 8),
                  A + (size_t)(m0 + row) * H_DIM + k0 + ch * 8, (m0 + row) < M);
        }
        c = tid;
        #pragma unroll
        for (int i = 0; i < 2; i++, c += 512) {         // B: 64 rows x 16 chunks
            int row = c >> 4, ch = c & 15;
            size_t off = (size_t)(k0 + row) * F + n0 + ch * 8;
            cp16(sptr(Bgs + row * BSTR + ch * 8), Bg + off);
            cp16(sptr(Bus + row * BSTR + ch * 8), Bu + off);
        }
    };

    float accg[2][4][4], accu[2][4][4];
    #pragma unroll
    for (int a = 0; a < 2; a++)
        #pragma unroll
        for (int b = 0; b < 4; b++)
            #pragma unroll
            for (int c = 0; c < 4; c++) { accg[a][b][c] = 0.f; accu[a][b][c] = 0.f; }

    const int KT = H_DIM / BK;
    load_stage(0, 0); CP_COMMIT;
    load_stage(1, BK); CP_COMMIT;

    const int t8 = lane >> 3, r8 = lane & 7;
    const int aRow = wm * 32 + (t8 & 1) * 8 + r8;       // + mf*16
    const int aCol = (t8 >> 1) * 8;                     // + kk
    const int bRowT = (t8 & 1) * 8 + r8;                // + kk   (trans: k index)
    const int bColT = wn * 32 + (t8 >> 1) * 8;          // + p*16 (n index)

    for (int it = 0; it < KT; ++it) {
        CP_WAIT1;
        __syncthreads();
        int pf = it + STAGES - 1;
        if (pf < KT) load_stage(pf % STAGES, pf * BK);
        CP_COMMIT;

        const __half* As  = smem + (it % STAGES) * GU_STAGE_H;
        const __half* Bgs = As + A_H;
        const __half* Bus = Bgs + B_H;

        #pragma unroll
        for (int kk = 0; kk < BK; kk += 16) {
            uint32_t a[2][4];
            ldm_x4(a[0], sptr(As + (aRow)      * KSTR + kk + aCol));
            ldm_x4(a[1], sptr(As + (aRow + 16) * KSTR + kk + aCol));
            #pragma unroll
            for (int p = 0; p < 2; p++) {
                uint32_t bg[4], bu[4];
                uint32_t boff = (kk + bRowT) * BSTR + bColT + p * 16;
                ldm_x4t(bg, sptr(Bgs + boff));
                ldm_x4t(bu, sptr(Bus + boff));
                #pragma unroll
                for (int h = 0; h < 2; h++) {
                    int nf = p * 2 + h;
                    mma16816(accg[0][nf], a[0], &bg[h * 2]);
                    mma16816(accg[1][nf], a[1], &bg[h * 2]);
                    mma16816(accu[0][nf], a[0], &bu[h * 2]);
                    mma16816(accu[1][nf], a[1], &bu[h * 2]);
                }
            }
        }
    }

    // epilogue: h = silu(g) * u -> fp16
    #pragma unroll
    for (int mf = 0; mf < 2; mf++) {
        #pragma unroll
        for (int nf = 0; nf < 4; nf++) {
            int row0 = m0 + wm * 32 + mf * 16 + (lane >> 2);
            int col  = n0 + wn * 32 + (nf >> 1) * 16 + (nf & 1) * 8 + (lane & 3) * 2;
            float* g = accg[mf][nf];
            float* u = accu[mf][nf];
            if (row0 < M) {
                float h0 = silu_f(g[0]) * u[0];
                float h1 = silu_f(g[1]) * u[1];
                *(__half2*)&Hout[(size_t)row0 * F + col] = __floats2half2_rn(h0, h1);
            }
            int row1 = row0 + 8;
            if (row1 < M) {
                float h2 = silu_f(g[2]) * u[2];
                float h3 = silu_f(g[3]) * u[3];
                *(__half2*)&Hout[(size_t)row1 * F + col] = __floats2half2_rn(h2, h3);
            }
        }
    }
}

// ---------------- kernel: down GEMM ------------------------------------------
// C tile 128x128 over N = H_DIM, K = F or FS. B = Wd natural [k][n=H].
template <bool ROUTED>
__global__ __launch_bounds__(512, 1)
void moe_down_kernel(const __half* __restrict__ Hbase,
                     const __half* __restrict__ WdAll,
                     float* __restrict__ outDirect,
                     const int* __restrict__ cnt,
                     float* __restrict__ Yr,
                     int K) {
    const int e = blockIdx.z;
    int M;
    const __half *A, *B;
    if (ROUTED) {
        M = cnt[e];
        A = Hbase + (size_t)e * CAP * K;
        B = WdAll + (size_t)e * (size_t)K * H_DIM;
    } else {
        M = T_NUM; A = Hbase; B = WdAll;
    }
    const int m0 = blockIdx.x * BM;
    if (m0 >= M) return;
    const int n0 = blockIdx.y * BN;

    extern __shared__ __half smem[];
    const int tid = threadIdx.x;
    const int lane = tid & 31;
    const int warp = tid >> 5;
    const int wm = warp >> 2, wn = warp & 3;

    auto load_stage = [&](int s, int k0) {
        __half* As = smem + s * DN_STAGE_H;
        __half* Bs = As + A_H;
        int c = tid;
        #pragma unroll
        for (int i = 0; i < 2; i++, c += 512) {
            int row = c >> 3, ch = c & 7;
            cp16z(sptr(As + row * KSTR + ch * 8),
                  A + (size_t)(m0 + row) * K + k0 + ch * 8, (m0 + row) < M);
        }
        c = tid;
        #pragma unroll
        for (int i = 0; i < 2; i++, c += 512) {
            int row = c >> 4, ch = c & 15;
            cp16(sptr(Bs + row * BSTR + ch * 8),
                 B + (size_t)(k0 + row) * H_DIM + n0 + ch * 8);
        }
    };

    float acc[2][4][4];
    #pragma unroll
    for (int a = 0; a < 2; a++)
        #pragma unroll
        for (int b = 0; b < 4; b++)
            #pragma unroll
            for (int c = 0; c < 4; c++) acc[a][b][c] = 0.f;

    const int KT = K / BK;
    load_stage(0, 0); CP_COMMIT;
    load_stage(1, BK); CP_COMMIT;

    const int t8 = lane >> 3, r8 = lane & 7;
    const int aRow = wm * 32 + (t8 & 1) * 8 + r8;
    const int aCol = (t8 >> 1) * 8;
    const int bRowT = (t8 & 1) * 8 + r8;
    const int bColT = wn * 32 + (t8 >> 1) * 8;

    for (int it = 0; it < KT; ++it) {
        CP_WAIT1;
        __syncthreads();
        int pf = it + STAGES - 1;
        if (pf < KT) load_stage(pf % STAGES, pf * BK);
        CP_COMMIT;

        const __half* As = smem + (it % STAGES) * DN_STAGE_H;
        const __half* Bs = As + A_H;

        #pragma unroll
        for (int kk = 0; kk < BK; kk += 16) {
            uint32_t a[2][4];
            ldm_x4(a[0], sptr(As + (aRow)      * KSTR + kk + aCol));
            ldm_x4(a[1], sptr(As + (aRow + 16) * KSTR + kk + aCol));
            #pragma unroll
            for (int p = 0; p < 2; p++) {
                uint32_t b[4];
                ldm_x4t(b, sptr(Bs + (kk + bRowT) * BSTR + bColT + p * 16));
                #pragma unroll
                for (int h = 0; h < 2; h++) {
                    int nf = p * 2 + h;
                    mma16816(acc[0][nf], a[0], &b[h * 2]);
                    mma16816(acc[1][nf], a[1], &b[h * 2]);
                }
            }
        }
    }

    #pragma unroll
    for (int mf = 0; mf < 2; mf++) {
        #pragma unroll
        for (int nf = 0; nf < 4; nf++) {
            int row0 = m0 + wm * 32 + mf * 16 + (lane >> 2);
            int col  = n0 + wn * 32 + (nf >> 1) * 16 + (nf & 1) * 8 + (lane & 3) * 2;
            float* c = acc[mf][nf];
            if (ROUTED) {
                if (row0 < M) {
                    float2 v = {c[0], c[1]};
                    *(float2*)&Yr[(size_t)(e * CAP + row0) * H_DIM + col] = v;
                }
                int row1 = row0 + 8;
                if (row1 < M) {
                    float2 v = {c[2], c[3]};
                    *(float2*)&Yr[(size_t)(e * CAP + row1) * H_DIM + col] = v;
                }
            } else {
                float2 v0 = {c[0], c[1]};
                float2 v1 = {c[2], c[3]};
                *(float2*)&outDirect[(size_t)row0 * H_DIM + col] = v0;
                *(float2*)&outDirect[(size_t)(row0 + 8) * H_DIM + col] = v1;
            }
        }
    }
}

// ---------------- kernel: combine routed contributions -----------------------
__global__ void moe_combine_kernel(float* __restrict__ out,
                                   const float* __restrict__ Yr,
                                   const int* __restrict__ t2s,
                                   const float* __restrict__ t2w) {
    const int t = blockIdx.x;
    const int s0 = t2s[t * TOPK + 0], s1 = t2s[t * TOPK + 1];
    const int s2 = t2s[t * TOPK + 2], s3 = t2s[t * TOPK + 3];
    const float w0 = t2w[t * TOPK + 0], w1 = t2w[t * TOPK + 1];
    const float w2 = t2w[t * TOPK + 2], w3 = t2w[t * TOPK + 3];
    float4* o = (float4*)(out + (size_t)t * H_DIM);
    const float4* y0 = (const float4*)(Yr + (size_t)s0 * H_DIM);
    const float4* y1 = (const float4*)(Yr + (size_t)s1 * H_DIM);
    const float4* y2 = (const float4*)(Yr + (size_t)s2 * H_DIM);
    const float4* y3 = (const float4*)(Yr + (size_t)s3 * H_DIM);
    for (int i = threadIdx.x; i < H_DIM / 4; i += 256) {
        float4 v = o[i];
        float4 a0 = y0[i], a1 = y1[i], a2 = y2[i], a3 = y3[i];
        v.x += w0 * a0.x + w1 * a1.x + w2 * a2.x + w3 * a3.x;
        v.y += w0 * a0.y + w1 * a1.y + w2 * a2.y + w3 * a3.y;
        v.z += w0 * a0.z + w1 * a1.z + w2 * a2.z + w3 * a3.z;
        v.w += w0 * a0.w + w1 * a1.w + w2 * a2.w + w3 * a3.w;
        o[i] = v;
    }
}

// ---------------- launch -----------------------------------------------------
extern "C" void kernel_launch(void* const* d_in, const int* in_sizes, int n_in,
                              void* d_out, int out_size) {
    const float* x   = (const float*)d_in[0];
    const float* wr  = (const float*)d_in[1];
    const float* Wg  = (const float*)d_in[2];
    const float* Wu  = (const float*)d_in[3];
    const float* Wd  = (const float*)d_in[4];
    const float* Wgs = (const float*)d_in[5];
    const float* Wus = (const float*)d_in[6];
    const float* Wds = (const float*)d_in[7];
    float* out = (float*)d_out;

    __half *Xg, *xh, *hr, *hs, *WgH, *WuH, *WdH, *WgsH, *WusH, *WdsH;
    float *Yr, *t2w;
    int *cnt, *t2s;
    cudaGetSymbolAddress((void**)&Xg,   d_Xg);
    cudaGetSymbolAddress((void**)&xh,   d_xh);
    cudaGetSymbolAddress((void**)&hr,   d_hr);
    cudaGetSymbolAddress((void**)&hs,   d_hs);
    cudaGetSymbolAddress((void**)&Yr,   d_Yr);
    cudaGetSymbolAddress((void**)&WgH,  d_WgH);
    cudaGetSymbolAddress((void**)&WuH,  d_WuH);
    cudaGetSymbolAddress((void**)&WdH,  d_WdH);
    cudaGetSymbolAddress((void**)&WgsH, d_WgsH);
    cudaGetSymbolAddress((void**)&WusH, d_WusH);
    cudaGetSymbolAddress((void**)&WdsH, d_WdsH);
    cudaGetSymbolAddress((void**)&cnt,  d_cnt);
    cudaGetSymbolAddress((void**)&t2s,  d_t2s);
    cudaGetSymbolAddress((void**)&t2w,  d_t2w);

    cudaFuncSetAttribute(moe_gu_kernel<true>,  cudaFuncAttributeMaxDynamicSharedMemorySize, GU_SMEM);
    cudaFuncSetAttribute(moe_gu_kernel<false>, cudaFuncAttributeMaxDynamicSharedMemorySize, GU_SMEM);
    cudaFuncSetAttribute(moe_down_kernel<true>,  cudaFuncAttributeMaxDynamicSharedMemorySize, DN_SMEM);
    cudaFuncSetAttribute(moe_down_kernel<false>, cudaFuncAttributeMaxDynamicSharedMemorySize, DN_SMEM);

    // weight converts (fp32 -> fp16, natural layout)
    size_t nE = (size_t)E_NUM * H_DIM * F_DIM / 4;
    size_t nS = (size_t)H_DIM * FS_DIM / 4;
    convert3_f2h_kernel<<<dim3(4096, 1, 3), 256>>>(Wg, Wu, Wd, WgH, WuH, WdH, nE);
    convert3_f2h_kernel<<<dim3(2048, 1, 3), 256>>>(Wgs, Wus, Wds, WgsH, WusH, WdsH, nS);

    moe_zero_cnt_kernel<<<1, 32>>>(cnt);
    moe_router_kernel<<<T_NUM, 128>>>(x, wr, xh, Xg, cnt, t2s, t2w);

    moe_gu_kernel<true><<<dim3(CAP / BM, F_DIM / BN, E_NUM), 512, GU_SMEM>>>(
        Xg, WgH, WuH, hr, cnt, F_DIM);
    moe_gu_kernel<false><<<dim3(T_NUM / BM, FS_DIM / BN, 1), 512, GU_SMEM>>>(
        xh, WgsH, WusH, hs, nullptr, FS_DIM);

    moe_down_kernel<false><<<dim3(T_NUM / BM, H_DIM / BN, 1), 512, DN_SMEM>>>(
        hs, WdsH, out, nullptr, nullptr, FS_DIM);
    moe_down_kernel<true><<<dim3(CAP / BM, H_DIM / BN, E_NUM), 512, DN_SMEM>>>(
        hr, WdH, nullptr, cnt, Yr, F_DIM);

    moe_combine_kernel<<<T_NUM, 256>>>(out, Yr, t2s, t2w);
}